// round 1
// baseline (speedup 1.0000x reference)
#include <cuda_runtime.h>
#include <math.h>

// Problem constants (GptOssExperts: B=1, S=1024, H=D=2880, E=8)
#define TOK   1024
#define HDIM  2880
#define DDIM  2880
#define NEXP  8
#define GU    (2*DDIM)      // 5760 gate_up columns
#define ALPHA 1.702f
#define LIMIT 7.0f

// Activation scratch: act[e][t][d] = (up+1)*glu, 8*1024*2880 floats = 94.4 MB
__device__ float g_act[(size_t)NEXP * TOK * DDIM];

// ---------------------------------------------------------------------------
// Kernel A: for each expert e, gate_up GEMM + bias + SwiGLU epilogue -> g_act
//   gate_up[e,t,c] = sum_h x[t,h] * Wgu[e,h,c] + bgu[e,c]
//   gate = col 2d, up = col 2d+1
// Tile: 128 tokens x 64 d-pairs (=128 gu columns). 256 threads, KT=16.
// ---------------------------------------------------------------------------
__global__ __launch_bounds__(256, 2)
void gate_up_kernel(const float* __restrict__ x,
                    const float* __restrict__ Wgu,
                    const float* __restrict__ bgu)
{
    const int e  = blockIdx.z;
    const int m0 = blockIdx.y * 128;   // token base
    const int d0 = blockIdx.x * 64;    // d-pair base
    const int c0 = d0 * 2;             // gu column base

    __shared__ float As[16][128];      // As[k][m] = x[m0+m][k0+k]
    __shared__ float Bs[16][128];      // Bs[k][j] = Wgu[e][k0+k][c0+j]

    const int tid = threadIdx.x;
    const int tx  = tid & 15;          // 0..15 column group
    const int ty  = tid >> 4;          // 0..15 row group

    // A-tile loader mapping: m = tid%128, k quads {lk..lk+3, lk+8..lk+11}
    const int lm = tid & 127;
    const int lk = (tid >> 7) * 4;     // 0 or 4
    const float* xA = x + (size_t)(m0 + lm) * HDIM;

    // B-tile loader mapping: k = tid/16, j quads {bj, bj+64}
    const int bk = tid >> 4;
    const int bj = (tid & 15) * 4;
    const float* WB = Wgu + (size_t)e * HDIM * GU + c0;

    float4 pa0, pa1, pb0, pb1;
    {
        pa0 = *(const float4*)(xA + lk);
        pa1 = *(const float4*)(xA + lk + 8);
        const float* wr = WB + (size_t)bk * GU;
        pb0 = *(const float4*)(wr + bj);
        pb1 = *(const float4*)(wr + bj + 64);
    }

    float ag[8][4], au[8][4];
    #pragma unroll
    for (int i = 0; i < 8; ++i)
        #pragma unroll
        for (int j = 0; j < 4; ++j) { ag[i][j] = 0.f; au[i][j] = 0.f; }

    const int NT = HDIM / 16;          // 180
    for (int kt = 0; kt < NT; ++kt) {
        // commit prefetched tile to SMEM
        As[lk + 0][lm] = pa0.x;  As[lk + 1][lm] = pa0.y;
        As[lk + 2][lm] = pa0.z;  As[lk + 3][lm] = pa0.w;
        As[lk + 8][lm] = pa1.x;  As[lk + 9][lm] = pa1.y;
        As[lk +10][lm] = pa1.z;  As[lk +11][lm] = pa1.w;
        *(float4*)&Bs[bk][bj]      = pb0;
        *(float4*)&Bs[bk][bj + 64] = pb1;
        __syncthreads();

        if (kt + 1 < NT) {
            const int k0n = (kt + 1) * 16;
            pa0 = *(const float4*)(xA + k0n + lk);
            pa1 = *(const float4*)(xA + k0n + lk + 8);
            const float* wr = WB + (size_t)(k0n + bk) * GU;
            pb0 = *(const float4*)(wr + bj);
            pb1 = *(const float4*)(wr + bj + 64);
        }

        #pragma unroll
        for (int k = 0; k < 16; ++k) {
            float4 a0 = *(const float4*)&As[k][ty * 4];
            float4 a1 = *(const float4*)&As[k][ty * 4 + 64];
            float4 b0 = *(const float4*)&Bs[k][tx * 8];
            float4 b1 = *(const float4*)&Bs[k][tx * 8 + 4];
            float am[8] = {a0.x, a0.y, a0.z, a0.w, a1.x, a1.y, a1.z, a1.w};
            float gw[4] = {b0.x, b0.z, b1.x, b1.z};
            float uw[4] = {b0.y, b0.w, b1.y, b1.w};
            #pragma unroll
            for (int mi = 0; mi < 8; ++mi)
                #pragma unroll
                for (int di = 0; di < 4; ++di) {
                    ag[mi][di] = fmaf(am[mi], gw[di], ag[mi][di]);
                    au[mi][di] = fmaf(am[mi], uw[di], au[mi][di]);
                }
        }
        __syncthreads();
    }

    // Epilogue: bias + clamp + SwiGLU, store activation
    const float* bptr = bgu + (size_t)e * GU + c0;
    #pragma unroll
    for (int mi = 0; mi < 8; ++mi) {
        const int mloc = (mi < 4) ? (ty * 4 + mi) : (64 + ty * 4 + mi - 4);
        const int m    = m0 + mloc;
        float* ap = g_act + ((size_t)e * TOK + m) * DDIM + d0 + tx * 4;
        #pragma unroll
        for (int di = 0; di < 4; ++di) {
            const int j = tx * 8 + di * 2;
            float gate = ag[mi][di] + bptr[j];
            float up   = au[mi][di] + bptr[j + 1];
            gate = fminf(gate, LIMIT);
            up   = fminf(fmaxf(up, -LIMIT), LIMIT);
            // gate * sigmoid(ALPHA*gate) = gate / (1 + exp(-ALPHA*gate))
            float glu = gate / (1.0f + expf(-ALPHA * gate));
            ap[di] = (up + 1.0f) * glu;
        }
    }
}

// ---------------------------------------------------------------------------
// Kernel B: out[t,h] = sum_e rw[t,e] * ( sum_d act[e,t,d]*Wd[e,d,h] + bd[e,h] )
// rw folded into A-tile at load time; expert loop inside CTA (no atomics).
// Tile: 128 tokens x 64 h. 256 threads, KT=16.
// ---------------------------------------------------------------------------
__global__ __launch_bounds__(256, 2)
void down_kernel(const float* __restrict__ rw,
                 const float* __restrict__ Wd,
                 const float* __restrict__ bd,
                 float* __restrict__ out)
{
    const int m0 = blockIdx.y * 128;
    const int h0 = blockIdx.x * 64;

    __shared__ float As[16][128];      // As[k][m] = act[e][m0+m][k0+k] * rw[m,e]
    __shared__ float Bs[16][64];       // Bs[k][j] = Wd[e][k0+k][h0+j]

    const int tid = threadIdx.x;
    const int tx  = tid & 15;
    const int ty  = tid >> 4;

    const int lm = tid & 127;
    const int lk = (tid >> 7) * 4;

    const int bk = tid >> 4;
    const int bj = (tid & 15) * 4;

    float acc[8][4];
    #pragma unroll
    for (int i = 0; i < 8; ++i)
        #pragma unroll
        for (int j = 0; j < 4; ++j) acc[i][j] = 0.f;

    const int NT = DDIM / 16;          // 180

    for (int e = 0; e < NEXP; ++e) {
        const float* aA  = g_act + ((size_t)e * TOK + m0 + lm) * DDIM;
        const float  rws = rw[(size_t)(m0 + lm) * NEXP + e];
        const float* WB  = Wd + (size_t)e * DDIM * HDIM + h0;

        float4 pa0, pa1, pb0;
        pa0 = *(const float4*)(aA + lk);
        pa1 = *(const float4*)(aA + lk + 8);
        pb0 = *(const float4*)(WB + (size_t)bk * HDIM + bj);

        for (int kt = 0; kt < NT; ++kt) {
            As[lk + 0][lm] = pa0.x * rws;  As[lk + 1][lm] = pa0.y * rws;
            As[lk + 2][lm] = pa0.z * rws;  As[lk + 3][lm] = pa0.w * rws;
            As[lk + 8][lm] = pa1.x * rws;  As[lk + 9][lm] = pa1.y * rws;
            As[lk +10][lm] = pa1.z * rws;  As[lk +11][lm] = pa1.w * rws;
            *(float4*)&Bs[bk][bj] = pb0;
            __syncthreads();

            if (kt + 1 < NT) {
                const int k0n = (kt + 1) * 16;
                pa0 = *(const float4*)(aA + k0n + lk);
                pa1 = *(const float4*)(aA + k0n + lk + 8);
                pb0 = *(const float4*)(WB + (size_t)(k0n + bk) * HDIM + bj);
            }

            #pragma unroll
            for (int k = 0; k < 16; ++k) {
                float4 a0 = *(const float4*)&As[k][ty * 4];
                float4 a1 = *(const float4*)&As[k][ty * 4 + 64];
                float4 b0 = *(const float4*)&Bs[k][tx * 4];
                float am[8] = {a0.x, a0.y, a0.z, a0.w, a1.x, a1.y, a1.z, a1.w};
                float bm[4] = {b0.x, b0.y, b0.z, b0.w};
                #pragma unroll
                for (int mi = 0; mi < 8; ++mi)
                    #pragma unroll
                    for (int ji = 0; ji < 4; ++ji)
                        acc[mi][ji] = fmaf(am[mi], bm[ji], acc[mi][ji]);
            }
            __syncthreads();
        }
    }

    // Epilogue: add routing-weighted down bias, write output
    #pragma unroll
    for (int mi = 0; mi < 8; ++mi) {
        const int mloc = (mi < 4) ? (ty * 4 + mi) : (64 + ty * 4 + mi - 4);
        const int m    = m0 + mloc;
        #pragma unroll
        for (int ji = 0; ji < 4; ++ji) {
            const int h = h0 + tx * 4 + ji;
            float v = acc[mi][ji];
            #pragma unroll
            for (int e = 0; e < NEXP; ++e)
                v = fmaf(rw[(size_t)m * NEXP + e], bd[(size_t)e * HDIM + h], v);
            out[(size_t)m * HDIM + h] = v;
        }
    }
}

// ---------------------------------------------------------------------------
// Launch
// Inputs (metadata order):
//   0: hidden_states   float32 [1,1024,2880]
//   1: routing_weights float32 [1024,8]
//   2: gate_up_proj    float32 [8,2880,5760]
//   3: gate_up_bias    float32 [8,5760]
//   4: down_proj       float32 [8,2880,2880]
//   5: down_bias       float32 [8,2880]
// Output: float32 [1,1024,2880]
// ---------------------------------------------------------------------------
extern "C" void kernel_launch(void* const* d_in, const int* in_sizes, int n_in,
                              void* d_out, int out_size)
{
    const float* x   = (const float*)d_in[0];
    const float* rw  = (const float*)d_in[1];
    const float* Wgu = (const float*)d_in[2];
    const float* bgu = (const float*)d_in[3];
    const float* Wd  = (const float*)d_in[4];
    const float* bd  = (const float*)d_in[5];
    float* out = (float*)d_out;

    dim3 gridA(GU / 128, TOK / 128, NEXP);   // (45, 8, 8)
    gate_up_kernel<<<gridA, 256>>>(x, Wgu, bgu);

    dim3 gridB(HDIM / 64, TOK / 128);        // (45, 8)
    down_kernel<<<gridB, 256>>>(rw, Wd, bd, out);
}